// round 1
// baseline (speedup 1.0000x reference)
#include <cuda_runtime.h>
#include <math.h>
#include <stdint.h>

// Problem constants (shapes are fixed by the dataset; runtime values read from in_sizes)
#define NMAX 50000
#define EMAX 850000
#define F 128

// ---------------- scratch (device globals: no allocation allowed) ----------------
__device__ float d_xn[NMAX * F];      // L2-normalized features
__device__ float d_h [NMAX * F];      // activations between layers
__device__ float d_hw[NMAX * F];      // X @ W result
__device__ float d_sim[EMAX];
__device__ float d_adj[EMAX];         // base attention (layer 0), for gating
__device__ float d_w  [EMAX];         // current edge weights
__device__ float d_rowsum[NMAX];
__device__ int   d_degc[NMAX];
__device__ float d_degw[NMAX];
__device__ float d_dinv[NMAX];
__device__ int   d_hist[NMAX + 1];
__device__ int   d_colstart[NMAX + 1];
__device__ int   d_coff[NMAX];
__device__ int   d_csr_eid[EMAX];
__device__ int   d_blocksums[128];

// ---------------- helpers ----------------
__device__ __forceinline__ float warpSum(float v) {
    v += __shfl_xor_sync(0xffffffffu, v, 16);
    v += __shfl_xor_sync(0xffffffffu, v, 8);
    v += __shfl_xor_sync(0xffffffffu, v, 4);
    v += __shfl_xor_sync(0xffffffffu, v, 2);
    v += __shfl_xor_sync(0xffffffffu, v, 1);
    return v;
}
__device__ __forceinline__ float warpMax(float v) {
    v = fmaxf(v, __shfl_xor_sync(0xffffffffu, v, 16));
    v = fmaxf(v, __shfl_xor_sync(0xffffffffu, v, 8));
    v = fmaxf(v, __shfl_xor_sync(0xffffffffu, v, 4));
    v = fmaxf(v, __shfl_xor_sync(0xffffffffu, v, 2));
    v = fmaxf(v, __shfl_xor_sync(0xffffffffu, v, 1));
    return v;
}

// ---------------- CSR build ----------------
__global__ void zero_hist_kernel(int n) {
    int i = blockIdx.x * blockDim.x + threadIdx.x;
    if (i < n) d_hist[i] = 0;
}
__global__ void hist_kernel(const int* __restrict__ ecol, int E) {
    int e = blockIdx.x * blockDim.x + threadIdx.x;
    if (e < E) atomicAdd(&d_hist[ecol[e]], 1);
}
__global__ void scan1_kernel(int n) {
    __shared__ int tsum[256];
    int b = blockIdx.x, t = threadIdx.x;
    int base = b * 1024 + t * 4;
    int v0 = (base + 0 < n) ? d_hist[base + 0] : 0;
    int v1 = (base + 1 < n) ? d_hist[base + 1] : 0;
    int v2 = (base + 2 < n) ? d_hist[base + 2] : 0;
    int v3 = (base + 3 < n) ? d_hist[base + 3] : 0;
    int s0 = v0, s1 = s0 + v1, s2 = s1 + v2, s3 = s2 + v3;
    tsum[t] = s3;
    __syncthreads();
    for (int off = 1; off < 256; off <<= 1) {
        int x = (t >= off) ? tsum[t - off] : 0;
        __syncthreads();
        tsum[t] += x;
        __syncthreads();
    }
    int add = (t > 0) ? tsum[t - 1] : 0;
    if (base + 0 < n) d_colstart[base + 1] = s0 + add;
    if (base + 1 < n) d_colstart[base + 2] = s1 + add;
    if (base + 2 < n) d_colstart[base + 3] = s2 + add;
    if (base + 3 < n) d_colstart[base + 4] = s3 + add;
    if (t == 255) d_blocksums[b] = tsum[255];
}
__global__ void scan2_kernel(int nblocks) {
    if (blockIdx.x == 0 && threadIdx.x == 0) {
        int run = 0;
        for (int i = 0; i < nblocks; i++) {
            int t = d_blocksums[i];
            d_blocksums[i] = run;
            run += t;
        }
        d_colstart[0] = 0;
    }
}
__global__ void scan3_kernel(int n) {
    int i = blockIdx.x * blockDim.x + threadIdx.x;
    if (i < n) d_colstart[i + 1] += d_blocksums[i >> 10];
}
__global__ void copyoff_kernel(int n) {
    int i = blockIdx.x * blockDim.x + threadIdx.x;
    if (i < n) d_coff[i] = d_colstart[i];
}
__global__ void scatter_kernel(const int* __restrict__ ecol, int E) {
    int e = blockIdx.x * blockDim.x + threadIdx.x;
    if (e < E) {
        int c = ecol[e];
        int p = atomicAdd(&d_coff[c], 1);
        d_csr_eid[p] = e;
    }
}

// ---------------- per-layer kernels ----------------
__global__ void zero_nodes_kernel(int n) {
    int i = blockIdx.x * blockDim.x + threadIdx.x;
    if (i < n) {
        d_rowsum[i] = 0.f;
        d_degc[i]   = 0;
        d_degw[i]   = 0.f;
    }
}

// L2-normalize rows: one warp per node
__global__ void normalize_kernel(const float* __restrict__ X, int N) {
    int gid = blockIdx.x * blockDim.x + threadIdx.x;
    int node = gid >> 5;
    if (node >= N) return;
    int lane = gid & 31;
    float4 v = ((const float4*)(X + (size_t)node * F))[lane];
    float ss = v.x * v.x + v.y * v.y + v.z * v.z + v.w * v.w;
    ss = warpSum(ss);
    float inv = 1.f / fmaxf(sqrtf(ss), 1e-12f);
    v.x *= inv; v.y *= inv; v.z *= inv; v.w *= inv;
    ((float4*)(d_xn + (size_t)node * F))[lane] = v;
}

// Per-edge cosine sim + threshold; rowsum & nonzero-count via atomics. One warp per edge.
__global__ void sim_kernel(const int* __restrict__ erow, const int* __restrict__ ecol, int E) {
    int gid = blockIdx.x * blockDim.x + threadIdx.x;
    int e = gid >> 5;
    if (e >= E) return;
    int lane = gid & 31;
    int r = erow[e], c = ecol[e];
    float s = 0.f;
    if (r != c) {
        float4 av = ((const float4*)(d_xn + (size_t)r * F))[lane];
        float4 bv = ((const float4*)(d_xn + (size_t)c * F))[lane];
        s = av.x * bv.x + av.y * bv.y + av.z * bv.z + av.w * bv.w;
        s = warpSum(s);
        if (s < 0.1f) s = 0.f;
    }
    if (lane == 0) {
        d_sim[e] = s;
        if (s > 0.f) {
            atomicAdd(&d_rowsum[r], s);
            atomicAdd(&d_degc[r], 1);
        }
    }
}

// Per-edge: normalized weight -> exp -> (blend with base adj) -> degw accumulation
__global__ void weight_kernel(const int* __restrict__ erow, const int* __restrict__ ecol,
                              const float* __restrict__ gate, int layer, int E) {
    int e = blockIdx.x * blockDim.x + threadIdx.x;
    if (e >= E) return;
    int r = erow[e], c = ecol[e];
    float wraw;
    if (r == c) {
        wraw = 1.f / ((float)d_degc[r] + 1.f);
    } else {
        float s = d_sim[e];
        wraw = (s > 0.f) ? s / d_rowsum[r] : 0.f;
    }
    float en = expf(wraw);     // note: exp applied to ALL edges (exp(0)=1 for pruned)
    float wgt;
    if (layer == 0) {
        d_adj[e] = en;
        wgt = en;
    } else {
        float g = gate[layer - 1];
        wgt = g * d_adj[e] + (1.f - g) * en;
    }
    d_w[e] = wgt;
    atomicAdd(&d_degw[c], wgt);
}

__global__ void dinv_kernel(int N) {
    int i = blockIdx.x * blockDim.x + threadIdx.x;
    if (i < N) {
        float d = d_degw[i];
        d_dinv[i] = (d > 0.f) ? rsqrtf(d) : 0.f;
    }
}

// Tiled GEMM: Y(=d_hw) = X @ W.  256 thr, 8 warps x 4 rows, CT output cols per block-y.
template <int FOUT, int CT>
__global__ void __launch_bounds__(256) gemm_kernel(const float* __restrict__ X,
                                                   const float* __restrict__ Wg, int N) {
    __shared__ float Ws[128 * CT];
    __shared__ float Xs[8][4][128];
    int t = threadIdx.x, w = t >> 5, lane = t & 31;
    int ct0 = blockIdx.y * CT;
    for (int i = t; i < 128 * CT; i += 256) {
        int k = i / CT, c = i - k * CT;
        Ws[i] = Wg[k * FOUT + ct0 + c];
    }
    int rowBase = blockIdx.x * 32 + w * 4;
#pragma unroll
    for (int r = 0; r < 4; r++) {
        int row = rowBase + r;
        float4 v = make_float4(0.f, 0.f, 0.f, 0.f);
        if (row < N) v = ((const float4*)(X + (size_t)row * 128))[lane];
        *(float4*)&Xs[w][r][lane * 4] = v;
    }
    __syncthreads();
    const bool has1 = (lane + 32) < CT;
    float a0[4] = {0.f, 0.f, 0.f, 0.f};
    float a1[4] = {0.f, 0.f, 0.f, 0.f};
#pragma unroll 8
    for (int k = 0; k < 128; k++) {
        float w0 = Ws[k * CT + lane];
        float w1 = has1 ? Ws[k * CT + lane + 32] : 0.f;
#pragma unroll
        for (int r = 0; r < 4; r++) {
            float xv = Xs[w][r][k];
            a0[r] = fmaf(xv, w0, a0[r]);
            a1[r] = fmaf(xv, w1, a1[r]);
        }
    }
#pragma unroll
    for (int r = 0; r < 4; r++) {
        int row = rowBase + r;
        if (row < N) {
            d_hw[(size_t)row * FOUT + ct0 + lane] = a0[r];
            if (has1) d_hw[(size_t)row * FOUT + ct0 + lane + 32] = a1[r];
        }
    }
}

// Atomic-free aggregation via CSR gather: one warp per destination node, F=128.
__global__ void gather128_kernel(const float* __restrict__ bias, const int* __restrict__ erow,
                                 float* __restrict__ out, int N, int doRelu) {
    int gid = blockIdx.x * blockDim.x + threadIdx.x;
    int node = gid >> 5;
    if (node >= N) return;
    int lane = gid & 31;
    int p0 = d_colstart[node], p1 = d_colstart[node + 1];
    float dc = d_dinv[node];
    float4 acc = make_float4(0.f, 0.f, 0.f, 0.f);
    for (int p = p0; p < p1; p++) {
        int eid = d_csr_eid[p];
        int r = erow[eid];
        float nrm = d_dinv[r] * d_w[eid] * dc;
        float4 hv = ((const float4*)(d_hw + (size_t)r * 128))[lane];
        acc.x = fmaf(nrm, hv.x, acc.x);
        acc.y = fmaf(nrm, hv.y, acc.y);
        acc.z = fmaf(nrm, hv.z, acc.z);
        acc.w = fmaf(nrm, hv.w, acc.w);
    }
    float4 bv = ((const float4*)bias)[lane];
    acc.x += bv.x; acc.y += bv.y; acc.z += bv.z; acc.w += bv.w;
    if (doRelu) {
        acc.x = fmaxf(acc.x, 0.f);
        acc.y = fmaxf(acc.y, 0.f);
        acc.z = fmaxf(acc.z, 0.f);
        acc.w = fmaxf(acc.w, 0.f);
    }
    ((float4*)(out + (size_t)node * 128))[lane] = acc;
}

// Final layer: gather over 40 output classes + fused log_softmax. One warp per node.
__global__ void gather40_lsm_kernel(const float* __restrict__ bias, const int* __restrict__ erow,
                                    float* __restrict__ out, int N) {
    int gid = blockIdx.x * blockDim.x + threadIdx.x;
    int node = gid >> 5;
    if (node >= N) return;
    int lane = gid & 31;
    int p0 = d_colstart[node], p1 = d_colstart[node + 1];
    float dc = d_dinv[node];
    bool has1 = lane < 8;  // classes 32..39
    float a0 = 0.f, a1 = 0.f;
    for (int p = p0; p < p1; p++) {
        int eid = d_csr_eid[p];
        int r = erow[eid];
        float nrm = d_dinv[r] * d_w[eid] * dc;
        const float* hr = d_hw + (size_t)r * 40;
        a0 = fmaf(nrm, hr[lane], a0);
        if (has1) a1 = fmaf(nrm, hr[lane + 32], a1);
    }
    a0 += bias[lane];
    float v1 = -INFINITY;
    if (has1) { a1 += bias[lane + 32]; v1 = a1; }
    float m = warpMax(fmaxf(a0, v1));
    float s = expf(a0 - m) + (has1 ? expf(a1 - m) : 0.f);
    s = warpSum(s);
    float lse = m + logf(s);
    out[(size_t)node * 40 + lane] = a0 - lse;
    if (has1) out[(size_t)node * 40 + lane + 32] = a1 - lse;
}

// ---------------- driver ----------------
extern "C" void kernel_launch(void* const* d_in, const int* in_sizes, int n_in,
                              void* d_out, int out_size) {
    const float* x    = (const float*)d_in[0];
    const float* gate = (const float*)d_in[1];
    const float* W0   = (const float*)d_in[2];
    const float* b0   = (const float*)d_in[3];
    const float* W1   = (const float*)d_in[4];
    const float* b1   = (const float*)d_in[5];
    const float* W2   = (const float*)d_in[6];
    const float* b2   = (const float*)d_in[7];
    const int*   ei   = (const int*)d_in[8];

    int N = in_sizes[0] / F;
    int E = in_sizes[8] / 2;
    const int* erow = ei;
    const int* ecol = ei + E;
    float* out = (float*)d_out;

    void* hp_v = nullptr;
    cudaGetSymbolAddress(&hp_v, d_h);
    float* hp = (float*)hp_v;

    const int TB = 256;
    int blkN  = (N + TB - 1) / TB;
    int blkN1 = (N + 1 + TB - 1) / TB;
    int blkE  = (E + TB - 1) / TB;
    int blkWN = ((N * 32) + TB - 1) / TB;   // warp-per-node
    int blkWE = (int)(((long long)E * 32 + TB - 1) / TB);  // warp-per-edge
    int nchunks = (N + 1023) / 1024;

    // ---- CSR by destination (edges constant within a launch) ----
    zero_hist_kernel<<<blkN1, TB>>>(N + 1);
    hist_kernel<<<blkE, TB>>>(ecol, E);
    scan1_kernel<<<nchunks, 256>>>(N);
    scan2_kernel<<<1, 32>>>(nchunks);
    scan3_kernel<<<blkN, TB>>>(N);
    copyoff_kernel<<<blkN, TB>>>(N);
    scatter_kernel<<<blkE, TB>>>(ecol, E);

    dim3 ggrid128((N + 31) / 32, 2);  // CT=64 x 2 tiles
    dim3 ggrid40((N + 31) / 32, 1);   // CT=40

    // ---- layer 0 ----
    zero_nodes_kernel<<<blkN, TB>>>(N);
    normalize_kernel<<<blkWN, TB>>>(x, N);
    sim_kernel<<<blkWE, TB>>>(erow, ecol, E);
    weight_kernel<<<blkE, TB>>>(erow, ecol, gate, 0, E);
    dinv_kernel<<<blkN, TB>>>(N);
    gemm_kernel<128, 64><<<ggrid128, 256>>>(x, W0, N);
    gather128_kernel<<<blkWN, TB>>>(b0, erow, hp, N, 1);

    // ---- layer 1 ----
    zero_nodes_kernel<<<blkN, TB>>>(N);
    normalize_kernel<<<blkWN, TB>>>(hp, N);
    sim_kernel<<<blkWE, TB>>>(erow, ecol, E);
    weight_kernel<<<blkE, TB>>>(erow, ecol, gate, 1, E);
    dinv_kernel<<<blkN, TB>>>(N);
    gemm_kernel<128, 64><<<ggrid128, 256>>>(hp, W1, N);
    gather128_kernel<<<blkWN, TB>>>(b1, erow, hp, N, 1);

    // ---- layer 2 ----
    zero_nodes_kernel<<<blkN, TB>>>(N);
    normalize_kernel<<<blkWN, TB>>>(hp, N);
    sim_kernel<<<blkWE, TB>>>(erow, ecol, E);
    weight_kernel<<<blkE, TB>>>(erow, ecol, gate, 2, E);
    dinv_kernel<<<blkN, TB>>>(N);
    gemm_kernel<40, 40><<<ggrid40, 256>>>(hp, W2, N);
    gather40_lsm_kernel<<<blkWN, TB>>>(b2, erow, out, N);
}

// round 2
// speedup vs baseline: 1.3136x; 1.3136x over previous
#include <cuda_runtime.h>
#include <math.h>
#include <stdint.h>

#define NMAX 50000
#define EMAX 850000
#define F 128
#define NCH ((NMAX + 1023) / 1024)   // scan chunks (49)

// ---------------- scratch ----------------
__device__ float d_xn[NMAX * F];
__device__ float d_h [NMAX * F];
__device__ float d_hw[NMAX * F];
__device__ float d_sim[EMAX];
__device__ float d_adj[EMAX];          // base attention (exp), e-indexed
__device__ float d_wcsr[EMAX];         // current edge weight, col-CSR ordered
__device__ float d_rowsum[NMAX];
__device__ int   d_degc[NMAX];
__device__ float d_degw[NMAX];
__device__ float d_dinv[NMAX];
// two CSRs: [0]=by row, [1]=by col
__device__ int   d_hist2 [2 * (NMAX + 1)];
__device__ int   d_start2[2 * (NMAX + 1)];
__device__ int   d_coff2 [2 * NMAX];
__device__ int   d_bsum2 [2 * 64];
__device__ int   d_rcsr_eid[EMAX];     // row-CSR: edge id
__device__ int   d_rcsr_dst[EMAX];     // row-CSR: col endpoint
__device__ int   d_ccsr_src[EMAX];     // col-CSR: row endpoint
__device__ int   d_epos[EMAX];         // e -> position in col-CSR

// ---------------- helpers ----------------
__device__ __forceinline__ float warpSum(float v) {
    v += __shfl_xor_sync(0xffffffffu, v, 16);
    v += __shfl_xor_sync(0xffffffffu, v, 8);
    v += __shfl_xor_sync(0xffffffffu, v, 4);
    v += __shfl_xor_sync(0xffffffffu, v, 2);
    v += __shfl_xor_sync(0xffffffffu, v, 1);
    return v;
}
__device__ __forceinline__ float warpMax(float v) {
    v = fmaxf(v, __shfl_xor_sync(0xffffffffu, v, 16));
    v = fmaxf(v, __shfl_xor_sync(0xffffffffu, v, 8));
    v = fmaxf(v, __shfl_xor_sync(0xffffffffu, v, 4));
    v = fmaxf(v, __shfl_xor_sync(0xffffffffu, v, 2));
    v = fmaxf(v, __shfl_xor_sync(0xffffffffu, v, 1));
    return v;
}

// ---------------- CSR build (both CSRs, fused) ----------------
__global__ void zero_hist2_kernel() {
    int i = blockIdx.x * blockDim.x + threadIdx.x;
    if (i < 2 * (NMAX + 1)) d_hist2[i] = 0;
}
__global__ void hist2_kernel(const int* __restrict__ erow, const int* __restrict__ ecol, int E) {
    int e = blockIdx.x * blockDim.x + threadIdx.x;
    if (e < E) {
        atomicAdd(&d_hist2[erow[e]], 1);
        atomicAdd(&d_hist2[(NMAX + 1) + ecol[e]], 1);
    }
}
__global__ void scan1_kernel(int n) {
    __shared__ int tsum[256];
    int y = blockIdx.y;
    const int* hist = d_hist2 + y * (NMAX + 1);
    int* start = d_start2 + y * (NMAX + 1);
    int* bsum  = d_bsum2 + y * 64;
    int b = blockIdx.x, t = threadIdx.x;
    int base = b * 1024 + t * 4;
    int v0 = (base + 0 < n) ? hist[base + 0] : 0;
    int v1 = (base + 1 < n) ? hist[base + 1] : 0;
    int v2 = (base + 2 < n) ? hist[base + 2] : 0;
    int v3 = (base + 3 < n) ? hist[base + 3] : 0;
    int s0 = v0, s1 = s0 + v1, s2 = s1 + v2, s3 = s2 + v3;
    tsum[t] = s3;
    __syncthreads();
    for (int off = 1; off < 256; off <<= 1) {
        int x = (t >= off) ? tsum[t - off] : 0;
        __syncthreads();
        tsum[t] += x;
        __syncthreads();
    }
    int add = (t > 0) ? tsum[t - 1] : 0;
    if (base + 0 < n) start[base + 1] = s0 + add;
    if (base + 1 < n) start[base + 2] = s1 + add;
    if (base + 2 < n) start[base + 3] = s2 + add;
    if (base + 3 < n) start[base + 4] = s3 + add;
    if (t == 255) bsum[b] = tsum[255];
}
__global__ void scan2_kernel(int nblocks) {
    if (threadIdx.x == 0) {
        for (int y = 0; y < 2; y++) {
            int* bsum = d_bsum2 + y * 64;
            int run = 0;
            for (int i = 0; i < nblocks; i++) { int t = bsum[i]; bsum[i] = run; run += t; }
            d_start2[y * (NMAX + 1)] = 0;
        }
    }
}
__global__ void scan3_kernel(int n) {
    int y = blockIdx.y;
    int* start = d_start2 + y * (NMAX + 1);
    int* coff  = d_coff2 + y * NMAX;
    const int* bsum = d_bsum2 + y * 64;
    int i = blockIdx.x * blockDim.x + threadIdx.x;
    if (i < n) {
        int v = start[i + 1] + bsum[i >> 10];
        start[i + 1] = v;
        if (i + 1 < n) coff[i + 1] = v;
        if (i == 0) coff[0] = 0;
    }
}
__global__ void scatter2_kernel(const int* __restrict__ erow, const int* __restrict__ ecol, int E) {
    int e = blockIdx.x * blockDim.x + threadIdx.x;
    if (e < E) {
        int r = erow[e], c = ecol[e];
        int pr = atomicAdd(&d_coff2[r], 1);
        d_rcsr_eid[pr] = e;
        d_rcsr_dst[pr] = c;
        int pc = atomicAdd(&d_coff2[NMAX + c], 1);
        d_ccsr_src[pc] = r;
        d_epos[e] = pc;
    }
}

// ---------------- per-layer kernels ----------------
// L2-normalize rows (warp/node) + zero degw
__global__ void normalize_kernel(const float* __restrict__ X, int N) {
    int gid = blockIdx.x * blockDim.x + threadIdx.x;
    int node = gid >> 5;
    if (node >= N) return;
    int lane = gid & 31;
    float4 v = ((const float4*)(X + (size_t)node * F))[lane];
    float ss = v.x * v.x + v.y * v.y + v.z * v.z + v.w * v.w;
    ss = warpSum(ss);
    float inv = 1.f / fmaxf(sqrtf(ss), 1e-12f);
    v.x *= inv; v.y *= inv; v.z *= inv; v.w *= inv;
    ((float4*)(d_xn + (size_t)node * F))[lane] = v;
    if (lane == 0) d_degw[node] = 0.f;
}

// Row-CSR sim: warp per source node; xn[row] in registers. No atomics.
__global__ void sim_row_kernel(int N) {
    int gid = blockIdx.x * blockDim.x + threadIdx.x;
    int r = gid >> 5;
    if (r >= N) return;
    int lane = gid & 31;
    int p0 = d_start2[r], p1 = d_start2[r + 1];
    float4 xr = ((const float4*)(d_xn + (size_t)r * F))[lane];
    float rs = 0.f;
    int cnt = 0;
    for (int p = p0; p < p1; p++) {
        int c = d_rcsr_dst[p];
        if (c == r) continue;  // self-sim removed
        float4 xc = ((const float4*)(d_xn + (size_t)c * F))[lane];
        float s = xr.x * xc.x + xr.y * xc.y + xr.z * xc.z + xr.w * xc.w;
        s = warpSum(s);
        if (s < 0.1f) s = 0.f;
        if (lane == 0) d_sim[d_rcsr_eid[p]] = s;
        rs += s;
        cnt += (s > 0.f) ? 1 : 0;
    }
    if (lane == 0) {
        d_rowsum[r] = rs;
        d_degc[r] = cnt;
    }
}

// Per-edge: normalize -> exp -> blend -> write into col-CSR slot; degw atomics
__global__ void weight_kernel(const int* __restrict__ erow, const int* __restrict__ ecol,
                              const float* __restrict__ gate, int layer, int E) {
    int e = blockIdx.x * blockDim.x + threadIdx.x;
    if (e >= E) return;
    int r = erow[e], c = ecol[e];
    float wraw;
    if (r == c) {
        wraw = 1.f / ((float)d_degc[r] + 1.f);
    } else {
        float s = d_sim[e];
        wraw = (s > 0.f) ? s / d_rowsum[r] : 0.f;
    }
    float en = expf(wraw);   // exp applied to ALL edges (exp(0)=1 for pruned)
    float w;
    if (layer == 0) {
        d_adj[e] = en;
        w = en;
    } else {
        float g = gate[layer - 1];
        w = g * d_adj[e] + (1.f - g) * en;
    }
    d_wcsr[d_epos[e]] = w;
    atomicAdd(&d_degw[c], w);
}

__global__ void dinv_kernel(int N) {
    int i = blockIdx.x * blockDim.x + threadIdx.x;
    if (i < N) {
        float d = d_degw[i];
        d_dinv[i] = (d > 0.f) ? rsqrtf(d) : 0.f;
    }
}

// Tiled GEMM with dinv[row] epilogue scaling: hw[row] = dinv[row] * (X[row] @ W)
template <int FOUT, int CT>
__global__ void __launch_bounds__(256) gemm_kernel(const float* __restrict__ X,
                                                   const float* __restrict__ Wg, int N) {
    __shared__ float Ws[128 * CT];
    __shared__ float Xs[8][4][128];
    int t = threadIdx.x, w = t >> 5, lane = t & 31;
    int ct0 = blockIdx.y * CT;
    for (int i = t; i < 128 * CT; i += 256) {
        int k = i / CT, c = i - k * CT;
        Ws[i] = Wg[k * FOUT + ct0 + c];
    }
    int rowBase = blockIdx.x * 32 + w * 4;
#pragma unroll
    for (int r = 0; r < 4; r++) {
        int row = rowBase + r;
        float4 v = make_float4(0.f, 0.f, 0.f, 0.f);
        if (row < N) v = ((const float4*)(X + (size_t)row * 128))[lane];
        *(float4*)&Xs[w][r][lane * 4] = v;
    }
    __syncthreads();
    const bool has1 = (lane + 32) < CT;
    float a0[4] = {0.f, 0.f, 0.f, 0.f};
    float a1[4] = {0.f, 0.f, 0.f, 0.f};
#pragma unroll 8
    for (int k = 0; k < 128; k++) {
        float w0 = Ws[k * CT + lane];
        float w1 = has1 ? Ws[k * CT + lane + 32] : 0.f;
#pragma unroll
        for (int r = 0; r < 4; r++) {
            float xv = Xs[w][r][k];
            a0[r] = fmaf(xv, w0, a0[r]);
            a1[r] = fmaf(xv, w1, a1[r]);
        }
    }
#pragma unroll
    for (int r = 0; r < 4; r++) {
        int row = rowBase + r;
        if (row < N) {
            float sc = d_dinv[row];
            d_hw[(size_t)row * FOUT + ct0 + lane] = a0[r] * sc;
            if (has1) d_hw[(size_t)row * FOUT + ct0 + lane + 32] = a1[r] * sc;
        }
    }
}

// Atomic-free aggregation: warp per dest node; sequential src/weight streams.
__global__ void gather128_kernel(const float* __restrict__ bias, float* __restrict__ out,
                                 int N, int doRelu) {
    int gid = blockIdx.x * blockDim.x + threadIdx.x;
    int node = gid >> 5;
    if (node >= N) return;
    int lane = gid & 31;
    int p0 = d_start2[(NMAX + 1) + node], p1 = d_start2[(NMAX + 1) + node + 1];
    float dc = d_dinv[node];
    float4 acc = make_float4(0.f, 0.f, 0.f, 0.f);
    for (int p = p0; p < p1; p++) {
        int r = d_ccsr_src[p];
        float w = d_wcsr[p];
        float4 hv = ((const float4*)(d_hw + (size_t)r * 128))[lane];
        acc.x = fmaf(w, hv.x, acc.x);
        acc.y = fmaf(w, hv.y, acc.y);
        acc.z = fmaf(w, hv.z, acc.z);
        acc.w = fmaf(w, hv.w, acc.w);
    }
    float4 bv = ((const float4*)bias)[lane];
    acc.x = fmaf(acc.x, dc, bv.x);
    acc.y = fmaf(acc.y, dc, bv.y);
    acc.z = fmaf(acc.z, dc, bv.z);
    acc.w = fmaf(acc.w, dc, bv.w);
    if (doRelu) {
        acc.x = fmaxf(acc.x, 0.f);
        acc.y = fmaxf(acc.y, 0.f);
        acc.z = fmaxf(acc.z, 0.f);
        acc.w = fmaxf(acc.w, 0.f);
    }
    ((float4*)(out + (size_t)node * 128))[lane] = acc;
}

// Final layer: 40-class gather + fused log_softmax (warp/node)
__global__ void gather40_lsm_kernel(const float* __restrict__ bias, float* __restrict__ out, int N) {
    int gid = blockIdx.x * blockDim.x + threadIdx.x;
    int node = gid >> 5;
    if (node >= N) return;
    int lane = gid & 31;
    int p0 = d_start2[(NMAX + 1) + node], p1 = d_start2[(NMAX + 1) + node + 1];
    float dc = d_dinv[node];
    bool has1 = lane < 8;
    float a0 = 0.f, a1 = 0.f;
    for (int p = p0; p < p1; p++) {
        int r = d_ccsr_src[p];
        float w = d_wcsr[p];
        const float* hr = d_hw + (size_t)r * 40;
        a0 = fmaf(w, hr[lane], a0);
        if (has1) a1 = fmaf(w, hr[lane + 32], a1);
    }
    a0 = fmaf(a0, dc, bias[lane]);
    float v1 = -INFINITY;
    if (has1) { a1 = fmaf(a1, dc, bias[lane + 32]); v1 = a1; }
    float m = warpMax(fmaxf(a0, v1));
    float s = expf(a0 - m) + (has1 ? expf(a1 - m) : 0.f);
    s = warpSum(s);
    float lse = m + logf(s);
    out[(size_t)node * 40 + lane] = a0 - lse;
    if (has1) out[(size_t)node * 40 + lane + 32] = a1 - lse;
}

// ---------------- driver ----------------
extern "C" void kernel_launch(void* const* d_in, const int* in_sizes, int n_in,
                              void* d_out, int out_size) {
    const float* x    = (const float*)d_in[0];
    const float* gate = (const float*)d_in[1];
    const float* W0   = (const float*)d_in[2];
    const float* b0   = (const float*)d_in[3];
    const float* W1   = (const float*)d_in[4];
    const float* b1   = (const float*)d_in[5];
    const float* W2   = (const float*)d_in[6];
    const float* b2   = (const float*)d_in[7];
    const int*   ei   = (const int*)d_in[8];

    int N = in_sizes[0] / F;
    int E = in_sizes[8] / 2;
    const int* erow = ei;
    const int* ecol = ei + E;
    float* out = (float*)d_out;

    void* hp_v = nullptr;
    cudaGetSymbolAddress(&hp_v, d_h);
    float* hp = (float*)hp_v;

    const int TB = 256;
    int blkN  = (N + TB - 1) / TB;
    int blkE  = (E + TB - 1) / TB;
    int blkWN = ((N * 32) + TB - 1) / TB;
    int blkZ  = (2 * (NMAX + 1) + TB - 1) / TB;
    int nchunks = (N + 1023) / 1024;

    // ---- build both CSRs ----
    zero_hist2_kernel<<<blkZ, TB>>>();
    hist2_kernel<<<blkE, TB>>>(erow, ecol, E);
    scan1_kernel<<<dim3(nchunks, 2), 256>>>(N);
    scan2_kernel<<<1, 32>>>(nchunks);
    scan3_kernel<<<dim3(blkN, 2), TB>>>(N);
    scatter2_kernel<<<blkE, TB>>>(erow, ecol, E);

    dim3 ggrid128((N + 31) / 32, 2);
    dim3 ggrid40((N + 31) / 32, 1);

    // ---- layer 0 ----
    normalize_kernel<<<blkWN, TB>>>(x, N);
    sim_row_kernel<<<blkWN, TB>>>(N);
    weight_kernel<<<blkE, TB>>>(erow, ecol, gate, 0, E);
    dinv_kernel<<<blkN, TB>>>(N);
    gemm_kernel<128, 64><<<ggrid128, 256>>>(x, W0, N);
    gather128_kernel<<<blkWN, TB>>>(b0, hp, N, 1);

    // ---- layer 1 ----
    normalize_kernel<<<blkWN, TB>>>(hp, N);
    sim_row_kernel<<<blkWN, TB>>>(N);
    weight_kernel<<<blkE, TB>>>(erow, ecol, gate, 1, E);
    dinv_kernel<<<blkN, TB>>>(N);
    gemm_kernel<128, 64><<<ggrid128, 256>>>(hp, W1, N);
    gather128_kernel<<<blkWN, TB>>>(b1, hp, N, 1);

    // ---- layer 2 ----
    normalize_kernel<<<blkWN, TB>>>(hp, N);
    sim_row_kernel<<<blkWN, TB>>>(N);
    weight_kernel<<<blkE, TB>>>(erow, ecol, gate, 2, E);
    dinv_kernel<<<blkN, TB>>>(N);
    gemm_kernel<40, 40><<<ggrid40, 256>>>(hp, W2, N);
    gather40_lsm_kernel<<<blkWN, TB>>>(b2, out, N);
}

// round 4
// speedup vs baseline: 1.3829x; 1.0527x over previous
#include <cuda_runtime.h>
#include <math.h>
#include <stdint.h>

#define NMAX 50000
#define EMAX 850000
#define F 128

// ---------------- scratch ----------------
__device__ float d_xn[NMAX * F];
__device__ float d_h [NMAX * F];
__device__ float d_hw[NMAX * F];
__device__ float d_simr[EMAX];         // sims, row-CSR ordered
__device__ float d_adjr[EMAX];         // base attention (exp), row-CSR ordered
__device__ float d_wcsr[EMAX];         // current edge weight, col-CSR ordered
__device__ float d_degw[NMAX];
// two CSRs: [0]=by row, [1]=by col
__device__ int   d_hist2 [2 * (NMAX + 1)];
__device__ int   d_start2[2 * (NMAX + 1)];
__device__ int   d_coff2 [2 * NMAX];
__device__ int   d_bsum2 [2 * 64];
__device__ int   d_rcsr_dst[EMAX];     // row-CSR: col endpoint
__device__ int   d_repos[EMAX];        // row-CSR pos -> col-CSR pos
__device__ int   d_ccsr_src[EMAX];     // col-CSR: row endpoint

// ---------------- helpers ----------------
__device__ __forceinline__ float warpSum(float v) {
    v += __shfl_xor_sync(0xffffffffu, v, 16);
    v += __shfl_xor_sync(0xffffffffu, v, 8);
    v += __shfl_xor_sync(0xffffffffu, v, 4);
    v += __shfl_xor_sync(0xffffffffu, v, 2);
    v += __shfl_xor_sync(0xffffffffu, v, 1);
    return v;
}
__device__ __forceinline__ float warpMax(float v) {
    v = fmaxf(v, __shfl_xor_sync(0xffffffffu, v, 16));
    v = fmaxf(v, __shfl_xor_sync(0xffffffffu, v, 8));
    v = fmaxf(v, __shfl_xor_sync(0xffffffffu, v, 4));
    v = fmaxf(v, __shfl_xor_sync(0xffffffffu, v, 2));
    v = fmaxf(v, __shfl_xor_sync(0xffffffffu, v, 1));
    return v;
}

// ---------------- CSR build ----------------
__global__ void zero_hist2_kernel() {
    int i = blockIdx.x * blockDim.x + threadIdx.x;
    if (i < 2 * (NMAX + 1)) d_hist2[i] = 0;
}
__global__ void hist2_kernel(const int* __restrict__ erow, const int* __restrict__ ecol, int E) {
    int e = blockIdx.x * blockDim.x + threadIdx.x;
    if (e < E) {
        atomicAdd(&d_hist2[erow[e]], 1);
        atomicAdd(&d_hist2[(NMAX + 1) + ecol[e]], 1);
    }
}
__global__ void scan1_kernel(int n) {
    __shared__ int tsum[256];
    int y = blockIdx.y;
    const int* hist = d_hist2 + y * (NMAX + 1);
    int* start = d_start2 + y * (NMAX + 1);
    int* bsum  = d_bsum2 + y * 64;
    int b = blockIdx.x, t = threadIdx.x;
    int base = b * 1024 + t * 4;
    int v0 = (base + 0 < n) ? hist[base + 0] : 0;
    int v1 = (base + 1 < n) ? hist[base + 1] : 0;
    int v2 = (base + 2 < n) ? hist[base + 2] : 0;
    int v3 = (base + 3 < n) ? hist[base + 3] : 0;
    int s0 = v0, s1 = s0 + v1, s2 = s1 + v2, s3 = s2 + v3;
    tsum[t] = s3;
    __syncthreads();
    for (int off = 1; off < 256; off <<= 1) {
        int x = (t >= off) ? tsum[t - off] : 0;
        __syncthreads();
        tsum[t] += x;
        __syncthreads();
    }
    int add = (t > 0) ? tsum[t - 1] : 0;
    if (base + 0 < n) start[base + 1] = s0 + add;
    if (base + 1 < n) start[base + 2] = s1 + add;
    if (base + 2 < n) start[base + 3] = s2 + add;
    if (base + 3 < n) start[base + 4] = s3 + add;
    if (t == 255) bsum[b] = tsum[255];
}
// warp-parallel scan of up to 64 block sums; warp y handles CSR y
__global__ void scan2_kernel(int nblocks) {
    int w = threadIdx.x >> 5, lane = threadIdx.x & 31;
    if (w >= 2) return;
    int* bsum = d_bsum2 + w * 64;
    int a = (lane < nblocks) ? bsum[lane] : 0;
    int b = (lane + 32 < nblocks) ? bsum[lane + 32] : 0;
#pragma unroll
    for (int off = 1; off < 32; off <<= 1) {
        int t = __shfl_up_sync(0xffffffffu, a, off);
        if (lane >= off) a += t;
    }
    int totalA = __shfl_sync(0xffffffffu, a, 31);
#pragma unroll
    for (int off = 1; off < 32; off <<= 1) {
        int t = __shfl_up_sync(0xffffffffu, b, off);
        if (lane >= off) b += t;
    }
    int exA = __shfl_up_sync(0xffffffffu, a, 1);
    int exB = __shfl_up_sync(0xffffffffu, b, 1);
    if (lane == 0) { exA = 0; exB = 0; }
    exB += totalA;             // FIX: second-half exclusive prefix needs first-half total for ALL lanes
    if (lane < nblocks) bsum[lane] = exA;
    if (lane + 32 < nblocks) bsum[lane + 32] = exB;
    if (lane == 0) d_start2[w * (NMAX + 1)] = 0;
}
__global__ void scan3_kernel(int n) {
    int y = blockIdx.y;
    int* start = d_start2 + y * (NMAX + 1);
    int* coff  = d_coff2 + y * NMAX;
    const int* bsum = d_bsum2 + y * 64;
    int i = blockIdx.x * blockDim.x + threadIdx.x;
    if (i < n) {
        int v = start[i + 1] + bsum[i >> 10];
        start[i + 1] = v;
        if (i + 1 < n) coff[i + 1] = v;
        if (i == 0) coff[0] = 0;
    }
}
__global__ void scatter2_kernel(const int* __restrict__ erow, const int* __restrict__ ecol, int E) {
    int e = blockIdx.x * blockDim.x + threadIdx.x;
    if (e < E) {
        int r = erow[e], c = ecol[e];
        int pr = atomicAdd(&d_coff2[r], 1);
        int pc = atomicAdd(&d_coff2[NMAX + c], 1);
        d_rcsr_dst[pr] = c;
        d_repos[pr] = pc;
        d_ccsr_src[pc] = r;
    }
}

// ---------------- per-layer kernels ----------------
// layer-0 only: L2-normalize x rows (warp/node) + zero degw
__global__ void normalize_kernel(const float* __restrict__ X, int N) {
    int gid = blockIdx.x * blockDim.x + threadIdx.x;
    int node = gid >> 5;
    if (node >= N) return;
    int lane = gid & 31;
    float4 v = ((const float4*)(X + (size_t)node * F))[lane];
    float ss = v.x * v.x + v.y * v.y + v.z * v.z + v.w * v.w;
    ss = warpSum(ss);
    float inv = 1.f / fmaxf(sqrtf(ss), 1e-12f);
    v.x *= inv; v.y *= inv; v.z *= inv; v.w *= inv;
    ((float4*)(d_xn + (size_t)node * F))[lane] = v;
    if (lane == 0) d_degw[node] = 0.f;
}

// Fused sim + weight: warp per source row.
// Pass 1: sims for this row's edges (row-CSR), rowsum+degc in registers.
// Pass 2: exp/blend, scatter weight into col-CSR slot, degw atomics.
__global__ void simweight_kernel(const float* __restrict__ gate, int layer, int N) {
    int gid = blockIdx.x * blockDim.x + threadIdx.x;
    int r = gid >> 5;
    if (r >= N) return;
    int lane = gid & 31;
    int p0 = d_start2[r], p1 = d_start2[r + 1];
    float4 xr = ((const float4*)(d_xn + (size_t)r * F))[lane];
    float rs = 0.f;
    int cnt = 0;
    int p = p0;
    for (; p + 1 < p1; p += 2) {
        int c0 = d_rcsr_dst[p], c1 = d_rcsr_dst[p + 1];
        float4 a = ((const float4*)(d_xn + (size_t)c0 * F))[lane];
        float4 b = ((const float4*)(d_xn + (size_t)c1 * F))[lane];
        float s0 = xr.x * a.x + xr.y * a.y + xr.z * a.z + xr.w * a.w;
        float s1 = xr.x * b.x + xr.y * b.y + xr.z * b.z + xr.w * b.w;
        s0 = warpSum(s0);
        s1 = warpSum(s1);
        if (c0 == r || s0 < 0.1f) s0 = 0.f;
        if (c1 == r || s1 < 0.1f) s1 = 0.f;
        if (lane == 0) { d_simr[p] = s0; d_simr[p + 1] = s1; }
        rs += s0 + s1;
        cnt += (s0 > 0.f) + (s1 > 0.f);
    }
    if (p < p1) {
        int c0 = d_rcsr_dst[p];
        float4 a = ((const float4*)(d_xn + (size_t)c0 * F))[lane];
        float s0 = xr.x * a.x + xr.y * a.y + xr.z * a.z + xr.w * a.w;
        s0 = warpSum(s0);
        if (c0 == r || s0 < 0.1f) s0 = 0.f;
        if (lane == 0) d_simr[p] = s0;
        rs += s0;
        cnt += (s0 > 0.f);
    }
    __syncwarp();
    // pass 2: lane-parallel over edges
    float lamw = 1.f / ((float)cnt + 1.f);
    float g = (layer > 0) ? gate[layer - 1] : 0.f;
    for (int q = p0 + lane; q < p1; q += 32) {
        int c = d_rcsr_dst[q];
        float wraw;
        if (c == r) {
            wraw = lamw;
        } else {
            float s = d_simr[q];
            wraw = (s > 0.f) ? s / rs : 0.f;
        }
        float en = expf(wraw);   // exp applied to ALL edges (exp(0)=1 for pruned)
        float w;
        if (layer == 0) {
            d_adjr[q] = en;
            w = en;
        } else {
            w = g * d_adjr[q] + (1.f - g) * en;
        }
        d_wcsr[d_repos[q]] = w;
        atomicAdd(&d_degw[c], w);
    }
}

// Tiled GEMM with inline rsqrt(degw[row]) epilogue: hw[row] = dinv[row]*(X[row]@W)
template <int FOUT, int CT>
__global__ void __launch_bounds__(256) gemm_kernel(const float* __restrict__ X,
                                                   const float* __restrict__ Wg, int N) {
    __shared__ float Ws[128 * CT];
    __shared__ float Xs[8][4][128];
    int t = threadIdx.x, w = t >> 5, lane = t & 31;
    int ct0 = blockIdx.y * CT;
    for (int i = t; i < 128 * CT; i += 256) {
        int k = i / CT, c = i - k * CT;
        Ws[i] = Wg[k * FOUT + ct0 + c];
    }
    int rowBase = blockIdx.x * 32 + w * 4;
#pragma unroll
    for (int r = 0; r < 4; r++) {
        int row = rowBase + r;
        float4 v = make_float4(0.f, 0.f, 0.f, 0.f);
        if (row < N) v = ((const float4*)(X + (size_t)row * 128))[lane];
        *(float4*)&Xs[w][r][lane * 4] = v;
    }
    __syncthreads();
    const bool has1 = (lane + 32) < CT;
    float a0[4] = {0.f, 0.f, 0.f, 0.f};
    float a1[4] = {0.f, 0.f, 0.f, 0.f};
#pragma unroll 8
    for (int k = 0; k < 128; k++) {
        float w0 = Ws[k * CT + lane];
        float w1 = has1 ? Ws[k * CT + lane + 32] : 0.f;
#pragma unroll
        for (int r = 0; r < 4; r++) {
            float xv = Xs[w][r][k];
            a0[r] = fmaf(xv, w0, a0[r]);
            a1[r] = fmaf(xv, w1, a1[r]);
        }
    }
#pragma unroll
    for (int r = 0; r < 4; r++) {
        int row = rowBase + r;
        if (row < N) {
            float dw = d_degw[row];
            float sc = (dw > 0.f) ? rsqrtf(dw) : 0.f;
            d_hw[(size_t)row * FOUT + ct0 + lane] = a0[r] * sc;
            if (has1) d_hw[(size_t)row * FOUT + ct0 + lane + 32] = a1[r] * sc;
        }
    }
}

// Fused aggregation + relu + L2-normalize (for next layer's sims) + degw re-zero.
__global__ void gather128_norm_kernel(const float* __restrict__ bias, float* __restrict__ out, int N) {
    int gid = blockIdx.x * blockDim.x + threadIdx.x;
    int node = gid >> 5;
    if (node >= N) return;
    int lane = gid & 31;
    int p0 = d_start2[(NMAX + 1) + node], p1 = d_start2[(NMAX + 1) + node + 1];
    float dw = d_degw[node];
    float dc = (dw > 0.f) ? rsqrtf(dw) : 0.f;
    float4 acc = make_float4(0.f, 0.f, 0.f, 0.f);
    int p = p0;
    for (; p + 1 < p1; p += 2) {
        int r0 = d_ccsr_src[p], r1 = d_ccsr_src[p + 1];
        float w0 = d_wcsr[p], w1 = d_wcsr[p + 1];
        float4 h0 = ((const float4*)(d_hw + (size_t)r0 * 128))[lane];
        float4 h1 = ((const float4*)(d_hw + (size_t)r1 * 128))[lane];
        acc.x = fmaf(w0, h0.x, fmaf(w1, h1.x, acc.x));
        acc.y = fmaf(w0, h0.y, fmaf(w1, h1.y, acc.y));
        acc.z = fmaf(w0, h0.z, fmaf(w1, h1.z, acc.z));
        acc.w = fmaf(w0, h0.w, fmaf(w1, h1.w, acc.w));
    }
    if (p < p1) {
        int r0 = d_ccsr_src[p];
        float w0 = d_wcsr[p];
        float4 h0 = ((const float4*)(d_hw + (size_t)r0 * 128))[lane];
        acc.x = fmaf(w0, h0.x, acc.x);
        acc.y = fmaf(w0, h0.y, acc.y);
        acc.z = fmaf(w0, h0.z, acc.z);
        acc.w = fmaf(w0, h0.w, acc.w);
    }
    float4 bv = ((const float4*)bias)[lane];
    acc.x = fmaxf(fmaf(acc.x, dc, bv.x), 0.f);
    acc.y = fmaxf(fmaf(acc.y, dc, bv.y), 0.f);
    acc.z = fmaxf(fmaf(acc.z, dc, bv.z), 0.f);
    acc.w = fmaxf(fmaf(acc.w, dc, bv.w), 0.f);
    ((float4*)(out + (size_t)node * 128))[lane] = acc;
    // fused L2-normalize for next layer
    float ss = acc.x * acc.x + acc.y * acc.y + acc.z * acc.z + acc.w * acc.w;
    ss = warpSum(ss);
    float inv = 1.f / fmaxf(sqrtf(ss), 1e-12f);
    float4 xv = make_float4(acc.x * inv, acc.y * inv, acc.z * inv, acc.w * inv);
    ((float4*)(d_xn + (size_t)node * F))[lane] = xv;
    if (lane == 0) d_degw[node] = 0.f;   // ready for next layer's weight pass
}

// Final layer: 40-class gather + fused log_softmax (warp/node)
__global__ void gather40_lsm_kernel(const float* __restrict__ bias, float* __restrict__ out, int N) {
    int gid = blockIdx.x * blockDim.x + threadIdx.x;
    int node = gid >> 5;
    if (node >= N) return;
    int lane = gid & 31;
    int p0 = d_start2[(NMAX + 1) + node], p1 = d_start2[(NMAX + 1) + node + 1];
    float dw = d_degw[node];
    float dc = (dw > 0.f) ? rsqrtf(dw) : 0.f;
    bool has1 = lane < 8;
    float a0 = 0.f, a1 = 0.f;
    for (int p = p0; p < p1; p++) {
        int r = d_ccsr_src[p];
        float w = d_wcsr[p];
        const float* hr = d_hw + (size_t)r * 40;
        a0 = fmaf(w, hr[lane], a0);
        if (has1) a1 = fmaf(w, hr[lane + 32], a1);
    }
    a0 = fmaf(a0, dc, bias[lane]);
    float v1 = -INFINITY;
    if (has1) { a1 = fmaf(a1, dc, bias[lane + 32]); v1 = a1; }
    float m = warpMax(fmaxf(a0, v1));
    float s = expf(a0 - m) + (has1 ? expf(a1 - m) : 0.f);
    s = warpSum(s);
    float lse = m + logf(s);
    out[(size_t)node * 40 + lane] = a0 - lse;
    if (has1) out[(size_t)node * 40 + lane + 32] = a1 - lse;
}

// ---------------- driver ----------------
extern "C" void kernel_launch(void* const* d_in, const int* in_sizes, int n_in,
                              void* d_out, int out_size) {
    const float* x    = (const float*)d_in[0];
    const float* gate = (const float*)d_in[1];
    const float* W0   = (const float*)d_in[2];
    const float* b0   = (const float*)d_in[3];
    const float* W1   = (const float*)d_in[4];
    const float* b1   = (const float*)d_in[5];
    const float* W2   = (const float*)d_in[6];
    const float* b2   = (const float*)d_in[7];
    const int*   ei   = (const int*)d_in[8];

    int N = in_sizes[0] / F;
    int E = in_sizes[8] / 2;
    const int* erow = ei;
    const int* ecol = ei + E;
    float* out = (float*)d_out;

    void* hp_v = nullptr;
    cudaGetSymbolAddress(&hp_v, d_h);
    float* hp = (float*)hp_v;

    const int TB = 256;
    int blkN  = (N + TB - 1) / TB;
    int blkE  = (E + TB - 1) / TB;
    int blkWN = ((N * 32) + TB - 1) / TB;
    int blkZ  = (2 * (NMAX + 1) + TB - 1) / TB;
    int nchunks = (N + 1023) / 1024;

    // ---- build both CSRs ----
    zero_hist2_kernel<<<blkZ, TB>>>();
    hist2_kernel<<<blkE, TB>>>(erow, ecol, E);
    scan1_kernel<<<dim3(nchunks, 2), 256>>>(N);
    scan2_kernel<<<1, 64>>>(nchunks);
    scan3_kernel<<<dim3(blkN, 2), TB>>>(N);
    scatter2_kernel<<<blkE, TB>>>(erow, ecol, E);

    dim3 ggrid128((N + 31) / 32, 2);
    dim3 ggrid40((N + 31) / 32, 1);

    // ---- layer 0 ----
    normalize_kernel<<<blkWN, TB>>>(x, N);
    simweight_kernel<<<blkWN, TB>>>(gate, 0, N);
    gemm_kernel<128, 64><<<ggrid128, 256>>>(x, W0, N);
    gather128_norm_kernel<<<blkWN, TB>>>(b0, hp, N);

    // ---- layer 1 ----
    simweight_kernel<<<blkWN, TB>>>(gate, 1, N);
    gemm_kernel<128, 64><<<ggrid128, 256>>>(hp, W1, N);
    gather128_norm_kernel<<<blkWN, TB>>>(b1, hp, N);

    // ---- layer 2 ----
    simweight_kernel<<<blkWN, TB>>>(gate, 2, N);
    gemm_kernel<40, 40><<<ggrid40, 256>>>(hp, W2, N);
    gather40_lsm_kernel<<<blkWN, TB>>>(b2, out, N);
}

// round 5
// speedup vs baseline: 1.3832x; 1.0002x over previous
#include <cuda_runtime.h>
#include <math.h>
#include <stdint.h>

#define NMAX 50000
#define EMAX 850000
#define F 128

// ---------------- scratch ----------------
__device__ float d_xn[NMAX * F];
__device__ float d_h [NMAX * F];
__device__ float d_hw[NMAX * F];
__device__ float d_simr[EMAX];         // sims, row-CSR ordered
__device__ float d_adjr[EMAX];         // base attention (exp), row-CSR ordered
__device__ float d_wcsr[EMAX];         // current edge weight, col-CSR ordered
__device__ float d_degw[NMAX];
// two CSRs: [0]=by row, [1]=by col
__device__ int   d_hist2 [2 * (NMAX + 1)];
__device__ int   d_start2[2 * (NMAX + 1)];
__device__ int   d_coff2 [2 * NMAX];
__device__ int   d_bsum2 [2 * 64];
__device__ int   d_rcsr_dst[EMAX];     // row-CSR: col endpoint
__device__ int   d_repos[EMAX];        // row-CSR pos -> col-CSR pos
__device__ int   d_ccsr_src[EMAX];     // col-CSR: row endpoint

// ---------------- helpers ----------------
__device__ __forceinline__ float warpSum(float v) {
    v += __shfl_xor_sync(0xffffffffu, v, 16);
    v += __shfl_xor_sync(0xffffffffu, v, 8);
    v += __shfl_xor_sync(0xffffffffu, v, 4);
    v += __shfl_xor_sync(0xffffffffu, v, 2);
    v += __shfl_xor_sync(0xffffffffu, v, 1);
    return v;
}
__device__ __forceinline__ float warpMax(float v) {
    v = fmaxf(v, __shfl_xor_sync(0xffffffffu, v, 16));
    v = fmaxf(v, __shfl_xor_sync(0xffffffffu, v, 8));
    v = fmaxf(v, __shfl_xor_sync(0xffffffffu, v, 4));
    v = fmaxf(v, __shfl_xor_sync(0xffffffffu, v, 2));
    v = fmaxf(v, __shfl_xor_sync(0xffffffffu, v, 1));
    return v;
}

// ---------------- CSR build ----------------
__global__ void zero_hist2_kernel() {
    int i = blockIdx.x * blockDim.x + threadIdx.x;
    if (i < 2 * (NMAX + 1)) d_hist2[i] = 0;
}
__global__ void hist2_kernel(const int* __restrict__ erow, const int* __restrict__ ecol, int E) {
    int e = blockIdx.x * blockDim.x + threadIdx.x;
    if (e < E) {
        atomicAdd(&d_hist2[erow[e]], 1);
        atomicAdd(&d_hist2[(NMAX + 1) + ecol[e]], 1);
    }
}
__global__ void scan1_kernel(int n) {
    __shared__ int tsum[256];
    int y = blockIdx.y;
    const int* hist = d_hist2 + y * (NMAX + 1);
    int* start = d_start2 + y * (NMAX + 1);
    int* bsum  = d_bsum2 + y * 64;
    int b = blockIdx.x, t = threadIdx.x;
    int base = b * 1024 + t * 4;
    int v0 = (base + 0 < n) ? hist[base + 0] : 0;
    int v1 = (base + 1 < n) ? hist[base + 1] : 0;
    int v2 = (base + 2 < n) ? hist[base + 2] : 0;
    int v3 = (base + 3 < n) ? hist[base + 3] : 0;
    int s0 = v0, s1 = s0 + v1, s2 = s1 + v2, s3 = s2 + v3;
    tsum[t] = s3;
    __syncthreads();
    for (int off = 1; off < 256; off <<= 1) {
        int x = (t >= off) ? tsum[t - off] : 0;
        __syncthreads();
        tsum[t] += x;
        __syncthreads();
    }
    int add = (t > 0) ? tsum[t - 1] : 0;
    if (base + 0 < n) start[base + 1] = s0 + add;
    if (base + 1 < n) start[base + 2] = s1 + add;
    if (base + 2 < n) start[base + 3] = s2 + add;
    if (base + 3 < n) start[base + 4] = s3 + add;
    if (t == 255) bsum[b] = tsum[255];
}
// warp-parallel scan of up to 64 block sums; warp y handles CSR y
__global__ void scan2_kernel(int nblocks) {
    int w = threadIdx.x >> 5, lane = threadIdx.x & 31;
    if (w >= 2) return;
    int* bsum = d_bsum2 + w * 64;
    int a = (lane < nblocks) ? bsum[lane] : 0;
    int b = (lane + 32 < nblocks) ? bsum[lane + 32] : 0;
#pragma unroll
    for (int off = 1; off < 32; off <<= 1) {
        int t = __shfl_up_sync(0xffffffffu, a, off);
        if (lane >= off) a += t;
    }
    int totalA = __shfl_sync(0xffffffffu, a, 31);
#pragma unroll
    for (int off = 1; off < 32; off <<= 1) {
        int t = __shfl_up_sync(0xffffffffu, b, off);
        if (lane >= off) b += t;
    }
    int exA = __shfl_up_sync(0xffffffffu, a, 1);
    int exB = __shfl_up_sync(0xffffffffu, b, 1);
    if (lane == 0) { exA = 0; exB = 0; }
    exB += totalA;             // FIX: second-half exclusive prefix needs first-half total for ALL lanes
    if (lane < nblocks) bsum[lane] = exA;
    if (lane + 32 < nblocks) bsum[lane + 32] = exB;
    if (lane == 0) d_start2[w * (NMAX + 1)] = 0;
}
__global__ void scan3_kernel(int n) {
    int y = blockIdx.y;
    int* start = d_start2 + y * (NMAX + 1);
    int* coff  = d_coff2 + y * NMAX;
    const int* bsum = d_bsum2 + y * 64;
    int i = blockIdx.x * blockDim.x + threadIdx.x;
    if (i < n) {
        int v = start[i + 1] + bsum[i >> 10];
        start[i + 1] = v;
        if (i + 1 < n) coff[i + 1] = v;
        if (i == 0) coff[0] = 0;
    }
}
__global__ void scatter2_kernel(const int* __restrict__ erow, const int* __restrict__ ecol, int E) {
    int e = blockIdx.x * blockDim.x + threadIdx.x;
    if (e < E) {
        int r = erow[e], c = ecol[e];
        int pr = atomicAdd(&d_coff2[r], 1);
        int pc = atomicAdd(&d_coff2[NMAX + c], 1);
        d_rcsr_dst[pr] = c;
        d_repos[pr] = pc;
        d_ccsr_src[pc] = r;
    }
}

// ---------------- per-layer kernels ----------------
// layer-0 only: L2-normalize x rows (warp/node) + zero degw
__global__ void normalize_kernel(const float* __restrict__ X, int N) {
    int gid = blockIdx.x * blockDim.x + threadIdx.x;
    int node = gid >> 5;
    if (node >= N) return;
    int lane = gid & 31;
    float4 v = ((const float4*)(X + (size_t)node * F))[lane];
    float ss = v.x * v.x + v.y * v.y + v.z * v.z + v.w * v.w;
    ss = warpSum(ss);
    float inv = 1.f / fmaxf(sqrtf(ss), 1e-12f);
    v.x *= inv; v.y *= inv; v.z *= inv; v.w *= inv;
    ((float4*)(d_xn + (size_t)node * F))[lane] = v;
    if (lane == 0) d_degw[node] = 0.f;
}

// Fused sim + weight: warp per source row.
// Pass 1: sims for this row's edges (row-CSR), rowsum+degc in registers.
// Pass 2: exp/blend, scatter weight into col-CSR slot, degw atomics.
__global__ void simweight_kernel(const float* __restrict__ gate, int layer, int N) {
    int gid = blockIdx.x * blockDim.x + threadIdx.x;
    int r = gid >> 5;
    if (r >= N) return;
    int lane = gid & 31;
    int p0 = d_start2[r], p1 = d_start2[r + 1];
    float4 xr = ((const float4*)(d_xn + (size_t)r * F))[lane];
    float rs = 0.f;
    int cnt = 0;
    int p = p0;
    for (; p + 1 < p1; p += 2) {
        int c0 = d_rcsr_dst[p], c1 = d_rcsr_dst[p + 1];
        float4 a = ((const float4*)(d_xn + (size_t)c0 * F))[lane];
        float4 b = ((const float4*)(d_xn + (size_t)c1 * F))[lane];
        float s0 = xr.x * a.x + xr.y * a.y + xr.z * a.z + xr.w * a.w;
        float s1 = xr.x * b.x + xr.y * b.y + xr.z * b.z + xr.w * b.w;
        s0 = warpSum(s0);
        s1 = warpSum(s1);
        if (c0 == r || s0 < 0.1f) s0 = 0.f;
        if (c1 == r || s1 < 0.1f) s1 = 0.f;
        if (lane == 0) { d_simr[p] = s0; d_simr[p + 1] = s1; }
        rs += s0 + s1;
        cnt += (s0 > 0.f) + (s1 > 0.f);
    }
    if (p < p1) {
        int c0 = d_rcsr_dst[p];
        float4 a = ((const float4*)(d_xn + (size_t)c0 * F))[lane];
        float s0 = xr.x * a.x + xr.y * a.y + xr.z * a.z + xr.w * a.w;
        s0 = warpSum(s0);
        if (c0 == r || s0 < 0.1f) s0 = 0.f;
        if (lane == 0) d_simr[p] = s0;
        rs += s0;
        cnt += (s0 > 0.f);
    }
    __syncwarp();
    // pass 2: lane-parallel over edges
    float lamw = 1.f / ((float)cnt + 1.f);
    float g = (layer > 0) ? gate[layer - 1] : 0.f;
    for (int q = p0 + lane; q < p1; q += 32) {
        int c = d_rcsr_dst[q];
        float wraw;
        if (c == r) {
            wraw = lamw;
        } else {
            float s = d_simr[q];
            wraw = (s > 0.f) ? s / rs : 0.f;
        }
        float en = expf(wraw);   // exp applied to ALL edges (exp(0)=1 for pruned)
        float w;
        if (layer == 0) {
            d_adjr[q] = en;
            w = en;
        } else {
            w = g * d_adjr[q] + (1.f - g) * en;
        }
        d_wcsr[d_repos[q]] = w;
        atomicAdd(&d_degw[c], w);
    }
}

// Tiled GEMM with inline rsqrt(degw[row]) epilogue: hw[row] = dinv[row]*(X[row]@W)
template <int FOUT, int CT>
__global__ void __launch_bounds__(256) gemm_kernel(const float* __restrict__ X,
                                                   const float* __restrict__ Wg, int N) {
    __shared__ float Ws[128 * CT];
    __shared__ float Xs[8][4][128];
    int t = threadIdx.x, w = t >> 5, lane = t & 31;
    int ct0 = blockIdx.y * CT;
    for (int i = t; i < 128 * CT; i += 256) {
        int k = i / CT, c = i - k * CT;
        Ws[i] = Wg[k * FOUT + ct0 + c];
    }
    int rowBase = blockIdx.x * 32 + w * 4;
#pragma unroll
    for (int r = 0; r < 4; r++) {
        int row = rowBase + r;
        float4 v = make_float4(0.f, 0.f, 0.f, 0.f);
        if (row < N) v = ((const float4*)(X + (size_t)row * 128))[lane];
        *(float4*)&Xs[w][r][lane * 4] = v;
    }
    __syncthreads();
    const bool has1 = (lane + 32) < CT;
    float a0[4] = {0.f, 0.f, 0.f, 0.f};
    float a1[4] = {0.f, 0.f, 0.f, 0.f};
#pragma unroll 8
    for (int k = 0; k < 128; k++) {
        float w0 = Ws[k * CT + lane];
        float w1 = has1 ? Ws[k * CT + lane + 32] : 0.f;
#pragma unroll
        for (int r = 0; r < 4; r++) {
            float xv = Xs[w][r][k];
            a0[r] = fmaf(xv, w0, a0[r]);
            a1[r] = fmaf(xv, w1, a1[r]);
        }
    }
#pragma unroll
    for (int r = 0; r < 4; r++) {
        int row = rowBase + r;
        if (row < N) {
            float dw = d_degw[row];
            float sc = (dw > 0.f) ? rsqrtf(dw) : 0.f;
            d_hw[(size_t)row * FOUT + ct0 + lane] = a0[r] * sc;
            if (has1) d_hw[(size_t)row * FOUT + ct0 + lane + 32] = a1[r] * sc;
        }
    }
}

// Fused aggregation + relu + L2-normalize (for next layer's sims) + degw re-zero.
__global__ void gather128_norm_kernel(const float* __restrict__ bias, float* __restrict__ out, int N) {
    int gid = blockIdx.x * blockDim.x + threadIdx.x;
    int node = gid >> 5;
    if (node >= N) return;
    int lane = gid & 31;
    int p0 = d_start2[(NMAX + 1) + node], p1 = d_start2[(NMAX + 1) + node + 1];
    float dw = d_degw[node];
    float dc = (dw > 0.f) ? rsqrtf(dw) : 0.f;
    float4 acc = make_float4(0.f, 0.f, 0.f, 0.f);
    int p = p0;
    for (; p + 1 < p1; p += 2) {
        int r0 = d_ccsr_src[p], r1 = d_ccsr_src[p + 1];
        float w0 = d_wcsr[p], w1 = d_wcsr[p + 1];
        float4 h0 = ((const float4*)(d_hw + (size_t)r0 * 128))[lane];
        float4 h1 = ((const float4*)(d_hw + (size_t)r1 * 128))[lane];
        acc.x = fmaf(w0, h0.x, fmaf(w1, h1.x, acc.x));
        acc.y = fmaf(w0, h0.y, fmaf(w1, h1.y, acc.y));
        acc.z = fmaf(w0, h0.z, fmaf(w1, h1.z, acc.z));
        acc.w = fmaf(w0, h0.w, fmaf(w1, h1.w, acc.w));
    }
    if (p < p1) {
        int r0 = d_ccsr_src[p];
        float w0 = d_wcsr[p];
        float4 h0 = ((const float4*)(d_hw + (size_t)r0 * 128))[lane];
        acc.x = fmaf(w0, h0.x, acc.x);
        acc.y = fmaf(w0, h0.y, acc.y);
        acc.z = fmaf(w0, h0.z, acc.z);
        acc.w = fmaf(w0, h0.w, acc.w);
    }
    float4 bv = ((const float4*)bias)[lane];
    acc.x = fmaxf(fmaf(acc.x, dc, bv.x), 0.f);
    acc.y = fmaxf(fmaf(acc.y, dc, bv.y), 0.f);
    acc.z = fmaxf(fmaf(acc.z, dc, bv.z), 0.f);
    acc.w = fmaxf(fmaf(acc.w, dc, bv.w), 0.f);
    ((float4*)(out + (size_t)node * 128))[lane] = acc;
    // fused L2-normalize for next layer
    float ss = acc.x * acc.x + acc.y * acc.y + acc.z * acc.z + acc.w * acc.w;
    ss = warpSum(ss);
    float inv = 1.f / fmaxf(sqrtf(ss), 1e-12f);
    float4 xv = make_float4(acc.x * inv, acc.y * inv, acc.z * inv, acc.w * inv);
    ((float4*)(d_xn + (size_t)node * F))[lane] = xv;
    if (lane == 0) d_degw[node] = 0.f;   // ready for next layer's weight pass
}

// Final layer: 40-class gather + fused log_softmax (warp/node)
__global__ void gather40_lsm_kernel(const float* __restrict__ bias, float* __restrict__ out, int N) {
    int gid = blockIdx.x * blockDim.x + threadIdx.x;
    int node = gid >> 5;
    if (node >= N) return;
    int lane = gid & 31;
    int p0 = d_start2[(NMAX + 1) + node], p1 = d_start2[(NMAX + 1) + node + 1];
    float dw = d_degw[node];
    float dc = (dw > 0.f) ? rsqrtf(dw) : 0.f;
    bool has1 = lane < 8;
    float a0 = 0.f, a1 = 0.f;
    for (int p = p0; p < p1; p++) {
        int r = d_ccsr_src[p];
        float w = d_wcsr[p];
        const float* hr = d_hw + (size_t)r * 40;
        a0 = fmaf(w, hr[lane], a0);
        if (has1) a1 = fmaf(w, hr[lane + 32], a1);
    }
    a0 = fmaf(a0, dc, bias[lane]);
    float v1 = -INFINITY;
    if (has1) { a1 = fmaf(a1, dc, bias[lane + 32]); v1 = a1; }
    float m = warpMax(fmaxf(a0, v1));
    float s = expf(a0 - m) + (has1 ? expf(a1 - m) : 0.f);
    s = warpSum(s);
    float lse = m + logf(s);
    out[(size_t)node * 40 + lane] = a0 - lse;
    if (has1) out[(size_t)node * 40 + lane + 32] = a1 - lse;
}

// ---------------- driver ----------------
extern "C" void kernel_launch(void* const* d_in, const int* in_sizes, int n_in,
                              void* d_out, int out_size) {
    const float* x    = (const float*)d_in[0];
    const float* gate = (const float*)d_in[1];
    const float* W0   = (const float*)d_in[2];
    const float* b0   = (const float*)d_in[3];
    const float* W1   = (const float*)d_in[4];
    const float* b1   = (const float*)d_in[5];
    const float* W2   = (const float*)d_in[6];
    const float* b2   = (const float*)d_in[7];
    const int*   ei   = (const int*)d_in[8];

    int N = in_sizes[0] / F;
    int E = in_sizes[8] / 2;
    const int* erow = ei;
    const int* ecol = ei + E;
    float* out = (float*)d_out;

    void* hp_v = nullptr;
    cudaGetSymbolAddress(&hp_v, d_h);
    float* hp = (float*)hp_v;

    const int TB = 256;
    int blkN  = (N + TB - 1) / TB;
    int blkE  = (E + TB - 1) / TB;
    int blkWN = ((N * 32) + TB - 1) / TB;
    int blkZ  = (2 * (NMAX + 1) + TB - 1) / TB;
    int nchunks = (N + 1023) / 1024;

    // ---- build both CSRs ----
    zero_hist2_kernel<<<blkZ, TB>>>();
    hist2_kernel<<<blkE, TB>>>(erow, ecol, E);
    scan1_kernel<<<dim3(nchunks, 2), 256>>>(N);
    scan2_kernel<<<1, 64>>>(nchunks);
    scan3_kernel<<<dim3(blkN, 2), TB>>>(N);
    scatter2_kernel<<<blkE, TB>>>(erow, ecol, E);

    dim3 ggrid128((N + 31) / 32, 2);
    dim3 ggrid40((N + 31) / 32, 1);

    // ---- layer 0 ----
    normalize_kernel<<<blkWN, TB>>>(x, N);
    simweight_kernel<<<blkWN, TB>>>(gate, 0, N);
    gemm_kernel<128, 64><<<ggrid128, 256>>>(x, W0, N);
    gather128_norm_kernel<<<blkWN, TB>>>(b0, hp, N);

    // ---- layer 1 ----
    simweight_kernel<<<blkWN, TB>>>(gate, 1, N);
    gemm_kernel<128, 64><<<ggrid128, 256>>>(hp, W1, N);
    gather128_norm_kernel<<<blkWN, TB>>>(b1, hp, N);

    // ---- layer 2 ----
    simweight_kernel<<<blkWN, TB>>>(gate, 2, N);
    gemm_kernel<40, 40><<<ggrid40, 256>>>(hp, W2, N);
    gather40_lsm_kernel<<<blkWN, TB>>>(b2, out, N);
}